// round 15
// baseline (speedup 1.0000x reference)
#include <cuda_runtime.h>
#include <cuda_fp16.h>

#define NB   16
#define CI   64
#define CM   32
#define HW   4096
#define NKV  1024

// Scratch (static device globals; no allocation allowed)
__device__ __half Qh[(size_t)NB * HW * CM];    // [B][4096 q][32 c]
__device__ __half Kh[(size_t)NB * NKV * CM];   // [B][1024 kv][32 c]
__device__ __half Vth[(size_t)NB * CM * NKV];  // [B][32 c][1024 kv]

// ---------------------------------------------------------------------------
// helpers
// ---------------------------------------------------------------------------
__device__ __forceinline__ unsigned smem_u32(const void* p) {
    return (unsigned)__cvta_generic_to_shared(p);
}

__device__ __forceinline__ void ldmx4(unsigned& r0, unsigned& r1, unsigned& r2,
                                      unsigned& r3, unsigned addr) {
    asm volatile("ldmatrix.sync.aligned.m8n8.x4.shared.b16 {%0,%1,%2,%3}, [%4];\n"
                 : "=r"(r0), "=r"(r1), "=r"(r2), "=r"(r3) : "r"(addr));
}

__device__ __forceinline__ void mma16816(float* dd, const unsigned* aa,
                                         const unsigned* bb, const float* cc) {
    asm volatile(
        "mma.sync.aligned.m16n8k16.row.col.f32.f16.f16.f32 "
        "{%0,%1,%2,%3},{%4,%5,%6,%7},{%8,%9},{%10,%11,%12,%13};\n"
        : "=f"(dd[0]), "=f"(dd[1]), "=f"(dd[2]), "=f"(dd[3])
        : "r"(aa[0]), "r"(aa[1]), "r"(aa[2]), "r"(aa[3]),
          "r"(bb[0]), "r"(bb[1]),
          "f"(cc[0]), "f"(cc[1]), "f"(cc[2]), "f"(cc[3]));
}

__device__ __forceinline__ unsigned packh2(float av, float bv) {
    __half2 hh = __floats2half2_rn(av, bv);
    return *(unsigned*)&hh;
}

__device__ __forceinline__ unsigned ex2h2(unsigned in) {
    unsigned r;
    asm("ex2.approx.f16x2 %0, %1;\n" : "=r"(r) : "r"(in));
    return r;
}

#define CP_ASYNC16(sa, g) \
    asm volatile("cp.async.cg.shared.global [%0], [%1], 16;\n" :: "r"(sa), "l"(g))
#define CP_COMMIT() asm volatile("cp.async.commit_group;\n")
#define CP_WAIT0()  asm volatile("cp.async.wait_group 0;\n" ::: "memory")
#define CP_WAIT1()  asm volatile("cp.async.wait_group 1;\n" ::: "memory")

#define L2E 1.4426950408889634f
#define ONES_H2 0x3C003C00u   // fp16 {1.0, 1.0}

// ---------------------------------------------------------------------------
// Kernel 1: qkv via tensor cores. 256 threads = 8 warps (16-px strip each).
// grid (32 row-pairs, B). 4 blocks/SM.
// ---------------------------------------------------------------------------
#define XSTR 72
#define WSTR 72
#define QKV_XSH   0
#define QKV_WSH   18432
#define QKV_BIAS  32256
#define SMEM1_BYTES (32256 + 384)

__global__ void __launch_bounds__(256, 4) qkv_kernel(
    const float* __restrict__ xg,
    const float* __restrict__ w_or, const float* __restrict__ b_or,
    const float* __restrict__ w_th, const float* __restrict__ b_th,
    const float* __restrict__ w_ph, const float* __restrict__ b_ph)
{
    extern __shared__ char smraw[];
    __half* xsh  = (__half*)(smraw + QKV_XSH);    // [128 px][XSTR]
    __half* wsh  = (__half*)(smraw + QKV_WSH);    // [96 out][WSTR]
    float*  bias = (float*)(smraw + QKV_BIAS);    // [96]
    float*  stg  = (float*)(smraw + QKV_XSH);     // alias: [128 px][33] fp32

    const int t    = threadIdx.x;
    const int warp = t >> 5;
    const int lane = t & 31;
    const int hp   = blockIdx.x;
    const int b    = blockIdx.y;

    // weights -> wsh (half): rows 0-31 theta, 32-63 phi, 64-95 origin
    for (int i = t; i < 2048; i += 256) {
        int r = i >> 6;
        int c = i & 63;
        wsh[r * WSTR + c]        = __float2half(w_th[i]);
        wsh[(32 + r) * WSTR + c] = __float2half(w_ph[i]);
        wsh[(64 + r) * WSTR + c] = __float2half(w_or[i]);
    }
    if (t < 32) {
        bias[t]      = b_th[t];
        bias[32 + t] = b_ph[t];
        bias[64 + t] = b_or[t];
    }

    // x tile: each thread loads 4 px x 8 ch as float4, packs, STS uint4
    {
        const int p0 = (t & 31) * 4;
        const int c0 = (t >> 5) * 8;
        const float* xb = xg + ((size_t)b * CI + c0) * HW + hp * 128 + p0;
        unsigned wbuf[4][4];
        #pragma unroll
        for (int cc = 0; cc < 4; ++cc) {
            float4 va = *(const float4*)xb;
            float4 vb = *(const float4*)(xb + HW);
            xb += 2 * HW;
            wbuf[0][cc] = packh2(va.x, vb.x);
            wbuf[1][cc] = packh2(va.y, vb.y);
            wbuf[2][cc] = packh2(va.z, vb.z);
            wbuf[3][cc] = packh2(va.w, vb.w);
        }
        #pragma unroll
        for (int j = 0; j < 4; ++j) {
            uint4 u0;
            u0.x = wbuf[j][0]; u0.y = wbuf[j][1]; u0.z = wbuf[j][2]; u0.w = wbuf[j][3];
            *(uint4*)&xsh[(p0 + j) * XSTR + c0] = u0;
        }
    }
    __syncthreads();

    // A fragments: warp px strip [warp*16, warp*16+15], 4 k-steps
    unsigned aX[4][4];
    {
        int arow = lane & 15;
        int acol = (lane >> 4) << 3;
        unsigned base = smem_u32(xsh);
        #pragma unroll
        for (int k = 0; k < 4; ++k) {
            unsigned ad = base +
                (((warp * 16 + arow) * XSTR + k * 16 + acol) << 1);
            ldmx4(aX[k][0], aX[k][1], aX[k][2], aX[k][3], ad);
        }
    }
    __syncthreads();   // xsh is now dead; stg may overwrite it

    const int brow = ((lane >> 4) << 3) + (lane & 7);
    const int bcol = ((lane >> 3) & 1) << 3;
    const unsigned wshBase = smem_u32(wsh);

    #pragma unroll 1
    for (int g = 0; g < 3; ++g) {
        float cf[4][4];
        #pragma unroll
        for (int nt = 0; nt < 4; ++nt) {
            cf[nt][0] = 0.f; cf[nt][1] = 0.f; cf[nt][2] = 0.f; cf[nt][3] = 0.f;
        }
        #pragma unroll
        for (int nt2 = 0; nt2 < 2; ++nt2) {
            #pragma unroll
            for (int k = 0; k < 4; ++k) {
                unsigned bw[4];
                unsigned ra = wshBase +
                    (((g * 32 + nt2 * 16 + brow) * WSTR + k * 16 + bcol) << 1);
                ldmx4(bw[0], bw[1], bw[2], bw[3], ra);
                mma16816(cf[nt2*2],   aX[k], &bw[0], cf[nt2*2]);
                mma16816(cf[nt2*2+1], aX[k], &bw[2], cf[nt2*2+1]);
            }
        }
        // add bias
        #pragma unroll
        for (int nt = 0; nt < 4; ++nt) {
            int o0 = g * 32 + nt * 8 + (lane & 3) * 2;
            cf[nt][0] += bias[o0];
            cf[nt][1] += bias[o0 + 1];
            cf[nt][2] += bias[o0];
            cf[nt][3] += bias[o0 + 1];
        }

        if (g == 0) {
            __half2* Qb = (__half2*)(Qh + ((size_t)b * HW + hp * 128) * CM);
            int row = warp * 16 + (lane >> 2);
            #pragma unroll
            for (int nt = 0; nt < 4; ++nt) {
                int cp = (nt * 8 + (lane & 3) * 2) >> 1;
                Qb[row * 16 + cp]       = __floats2half2_rn(cf[nt][0], cf[nt][1]);
                Qb[(row + 8) * 16 + cp] = __floats2half2_rn(cf[nt][2], cf[nt][3]);
            }
        } else {
            int row = warp * 16 + (lane >> 2);
            #pragma unroll
            for (int nt = 0; nt < 4; ++nt) {
                int c0 = nt * 8 + (lane & 3) * 2;
                stg[row * 33 + c0]           = cf[nt][0];
                stg[row * 33 + c0 + 1]       = cf[nt][1];
                stg[(row + 8) * 33 + c0]     = cf[nt][2];
                stg[(row + 8) * 33 + c0 + 1] = cf[nt][3];
            }
            __syncthreads();
            if (g == 1) {
                #pragma unroll
                for (int i = 0; i < 4; ++i) {
                    int idx = t + i * 256;
                    int kw = idx >> 5;
                    int o  = idx & 31;
                    float mv = fmaxf(
                        fmaxf(stg[(2*kw) * 33 + o], stg[(2*kw + 1) * 33 + o]),
                        fmaxf(stg[(64 + 2*kw) * 33 + o], stg[(65 + 2*kw) * 33 + o]));
                    Kh[((size_t)b * NKV + hp * 32 + kw) * CM + o] = __float2half(mv);
                }
            } else {
                #pragma unroll
                for (int i = 0; i < 4; ++i) {
                    int idx = t + i * 256;
                    int o  = idx >> 5;
                    int kw = idx & 31;
                    float mv = fmaxf(
                        fmaxf(stg[(2*kw) * 33 + o], stg[(2*kw + 1) * 33 + o]),
                        fmaxf(stg[(64 + 2*kw) * 33 + o], stg[(65 + 2*kw) * 33 + o]));
                    Vth[((size_t)b * CM + o) * NKV + hp * 32 + kw] = __float2half(mv);
                }
            }
            __syncthreads();
        }
    }
}

// ---------------------------------------------------------------------------
// Kernel 2: FUSED attention + output conv + residual.
// grid (32 q-tiles of 128, B), 256 threads = 8 warps, 3 blocks/SM.
// 128-kv buffers (3-stage, depth-2 prefetch), TWO 64-kv sub-iterations per
// buffer with NO barrier between them: 7 barriers/waits instead of 15.
// ---------------------------------------------------------------------------
#define QSTR 40
#define VSTR 136                   // 128 kv + 8 pad halfs (272B row stride)
#define OSTR 132
#define AT_QSM  0
#define AT_WSM  10240
#define AT_BSD  15360
#define AT_KSM  15616
#define KBUF_B  (128 * QSTR * 2)   // 10240 bytes per K buffer (128 kv rows)
#define VBUF_B  (32 * VSTR * 2)    // 8704 bytes per V buffer (128 kv cols)
#define AT_VSM  (AT_KSM + 3 * KBUF_B)          // 46336
#define AT_OSM  15616              // alias over Ksm/Vsm (dead after mainloop)
#define SMEM2_BYTES (AT_VSM + 3 * VBUF_B)      // 72448

__global__ void __launch_bounds__(256, 3) attn_kernel(
    const float* __restrict__ xg, const float* __restrict__ w_W,
    const float* __restrict__ b_W, float* __restrict__ outg)
{
    extern __shared__ char atraw[];
    __half* Qsm = (__half*)(atraw + AT_QSM);   // [128 q][QSTR]; Ysm in epilogue
    __half* wsm = (__half*)(atraw + AT_WSM);   // [64 out][QSTR]
    float*  bsd = (float*)(atraw + AT_BSD);    // [64]
    __half* Ksm = (__half*)(atraw + AT_KSM);   // 3 x [128 kv][QSTR]
    __half* Vsm = (__half*)(atraw + AT_VSM);   // 3 x [32 c][VSTR]
    float*  osm = (float*)(atraw + AT_OSM);    // [64 out][OSTR] (alias)
    __half* Ysm = Qsm;

    const int t    = threadIdx.x;
    const int warp = t >> 5;
    const int lane = t & 31;
    const int b    = blockIdx.y;
    const int q0   = blockIdx.x * 128;

    // Per-thread copy coordinates for one 128-kv chunk (2 cp.async each for K,V)
    // K: 128 rows x 4 segs of 16B; V: 32 rows x 16 segs of 16B (512 tasks each)
    const __half* kSrcB = Kh + (size_t)b * NKV * CM;
    const __half* vSrcB = Vth + (size_t)b * CM * NKV;

    // prologue: Q + chunk0 (group 0), chunk1 (group 1); w_W/b_W scalar loads
    {
        #pragma unroll
        for (int i = 0; i < 2; ++i) {
            int idx = t + i * 256;
            int row = idx >> 2;
            int seg = idx & 3;
            CP_ASYNC16(smem_u32(&Qsm[row * QSTR + seg * 8]),
                       Qh + ((size_t)b * HW + q0 + row) * CM + seg * 8);
        }
        #pragma unroll
        for (int i = 0; i < 2; ++i) {
            int idx = t + i * 256;
            int kr = idx >> 2, ks = idx & 3;
            CP_ASYNC16(smem_u32(&Ksm[kr * QSTR + ks * 8]),
                       kSrcB + (size_t)kr * CM + ks * 8);
            int vr = idx >> 4, vs = idx & 15;
            CP_ASYNC16(smem_u32(&Vsm[vr * VSTR + vs * 8]),
                       vSrcB + (size_t)vr * NKV + vs * 8);
        }
        CP_COMMIT();                               // group: Q + chunk 0
        #pragma unroll
        for (int i = 0; i < 2; ++i) {
            int idx = t + i * 256;
            int kr = idx >> 2, ks = idx & 3;
            CP_ASYNC16(smem_u32(&Ksm[kr * QSTR + ks * 8]) + KBUF_B,
                       kSrcB + (size_t)(kr + 128) * CM + ks * 8);
            int vr = idx >> 4, vs = idx & 15;
            CP_ASYNC16(smem_u32(&Vsm[vr * VSTR + vs * 8]) + VBUF_B,
                       vSrcB + (size_t)vr * NKV + 128 + vs * 8);
        }
        CP_COMMIT();                               // group: chunk 1
        for (int i = t; i < 2048; i += 256) {
            wsm[(i >> 5) * QSTR + (i & 31)] = __float2half(w_W[i]);
        }
        if (t < 64) {
            bsd[t] = b_W[t];
        }
        CP_WAIT1();                                // Q + chunk 0 complete
        __syncthreads();
    }

    // A-operand (Q) fragments for 2 k-steps
    unsigned aQ0[4];
    unsigned aQ1[4];
    {
        int arow = lane & 15;
        int acol = (lane >> 4) << 3;
        unsigned base = smem_u32(Qsm);
        unsigned ad0 = base + (((warp * 16 + arow) * QSTR + acol) << 1);
        ldmx4(aQ0[0], aQ0[1], aQ0[2], aQ0[3], ad0);
        ldmx4(aQ1[0], aQ1[1], aQ1[2], aQ1[3], ad0 + 32);
    }

    const int brow = ((lane >> 4) << 3) + (lane & 7);
    const int bcol = ((lane >> 3) & 1) << 3;
    const unsigned kLdm0 = smem_u32(Ksm) + ((brow * QSTR + bcol) << 1);
    const unsigned vLdm0 = smem_u32(Vsm) + ((brow * VSTR + bcol) << 1);

    // per-thread cp.async coords for the mainloop prefetch
    const int kRow = t >> 2;          // used with +256 second pass
    const int kSeg = t & 3;
    const int vRow = t >> 4;
    const int vSeg = t & 15;
    const unsigned kDstA = smem_u32(&Ksm[kRow * QSTR + kSeg * 8]);
    const unsigned kDstB = smem_u32(&Ksm[(kRow + 64) * QSTR + kSeg * 8]);
    const unsigned vDstA = smem_u32(&Vsm[vRow * VSTR + vSeg * 8]);
    const unsigned vDstB = smem_u32(&Vsm[(vRow + 16) * VSTR + vSeg * 8]);

    float oAcc[4][4];
    #pragma unroll
    for (int n = 0; n < 4; ++n) {
        oAcc[n][0] = 0.f; oAcc[n][1] = 0.f; oAcc[n][2] = 0.f; oAcc[n][3] = 0.f;
    }
    float lAcc[4];      // row-sum accumulator via ones-MMA: [0]=row lo, [2]=row hi
    lAcc[0] = 0.f; lAcc[1] = 0.f; lAcc[2] = 0.f; lAcc[3] = 0.f;
    const unsigned onesB[2] = { ONES_H2, ONES_H2 };

    float m_lo = -1e30f;
    float m_hi = -1e30f;

    unsigned kOffCur = 0, vOffCur = 0;
    unsigned kOffPre = 2 * KBUF_B, vOffPre = 2 * VBUF_B;

    for (int kc = 0; kc < 8; ++kc) {
        if (kc < 6) {
            const __half* kP = kSrcB + (size_t)(kc + 2) * 128 * CM;
            const __half* vP = vSrcB + (size_t)(kc + 2) * 128;
            CP_ASYNC16(kDstA + kOffPre, kP + (size_t)kRow * CM + kSeg * 8);
            CP_ASYNC16(kDstB + kOffPre, kP + (size_t)(kRow + 64) * CM + kSeg * 8);
            CP_ASYNC16(vDstA + vOffPre, vP + (size_t)vRow * NKV + vSeg * 8);
            CP_ASYNC16(vDstB + vOffPre, vP + (size_t)(vRow + 16) * NKV + vSeg * 8);
            CP_COMMIT();
            kOffPre = (kOffPre == 2 * KBUF_B) ? 0u : kOffPre + KBUF_B;
            vOffPre = (vOffPre == 2 * VBUF_B) ? 0u : vOffPre + VBUF_B;
        }
        const unsigned kLdmBuf = kLdm0 + kOffCur;
        const unsigned vLdmBuf = vLdm0 + vOffCur;
        kOffCur = (kOffCur == 2 * KBUF_B) ? 0u : kOffCur + KBUF_B;
        vOffCur = (vOffCur == 2 * VBUF_B) ? 0u : vOffCur + VBUF_B;

        // two 64-kv sub-iterations over this buffer, NO barrier between them
        #pragma unroll 1
        for (int h = 0; h < 2; ++h) {
            const unsigned kLdm = kLdmBuf + h * (64 * QSTR * 2);
            const unsigned vLdm = vLdmBuf + h * 128;   // +64 kv cols (128 B)

            // sAcc = Q K^T for this 64-kv sub-chunk
            float sAcc[8][4];
            #pragma unroll
            for (int j = 0; j < 8; ++j) {
                sAcc[j][0] = 0.f; sAcc[j][1] = 0.f;
                sAcc[j][2] = 0.f; sAcc[j][3] = 0.f;
            }
            #pragma unroll
            for (int g = 0; g < 4; ++g) {
                unsigned bkf[4];
                unsigned ra = kLdm + g * (16 * QSTR * 2);
                ldmx4(bkf[0], bkf[1], bkf[2], bkf[3], ra);
                mma16816(sAcc[2*g],   aQ0, &bkf[0], sAcc[2*g]);
                mma16816(sAcc[2*g+1], aQ0, &bkf[2], sAcc[2*g+1]);
                ldmx4(bkf[0], bkf[1], bkf[2], bkf[3], ra + 32);
                mma16816(sAcc[2*g],   aQ1, &bkf[0], sAcc[2*g]);
                mma16816(sAcc[2*g+1], aQ1, &bkf[2], sAcc[2*g+1]);
            }

            // local max per group
            float mlo = -1e30f;
            float mhi = -1e30f;
            #pragma unroll
            for (int j = 0; j < 8; ++j) {
                mlo = fmaxf(mlo, fmaxf(sAcc[j][0], sAcc[j][1]));
                mhi = fmaxf(mhi, fmaxf(sAcc[j][2], sAcc[j][3]));
            }

            // Deferred-max: skip reduce+rescale when warp max cannot move (exact)
            bool below = (mlo <= m_lo) && (mhi <= m_hi);
            if (!__all_sync(0xffffffffu, below)) {
                unsigned mp = packh2(mlo, mhi);
                __half2 mh = *(__half2*)&mp;
                unsigned ms1 = __shfl_xor_sync(0xffffffffu, mp, 1);
                mh = __hmax2(mh, *(__half2*)&ms1);
                unsigned mhu = *(unsigned*)&mh;
                unsigned ms2 = __shfl_xor_sync(0xffffffffu, mhu, 2);
                mh = __hmax2(mh, *(__half2*)&ms2);
                mlo = __low2float(mh);
                mhi = __high2float(mh);

                float nmlo = fmaxf(m_lo, mlo);
                float nmhi = fmaxf(m_hi, mhi);
                float sclo = __expf(m_lo - nmlo);
                float schi = __expf(m_hi - nmhi);
                m_lo = nmlo;
                m_hi = nmhi;

                bool noup = (sclo == 1.0f) && (schi == 1.0f);
                if (!__all_sync(0xffffffffu, noup)) {
                    #pragma unroll
                    for (int n = 0; n < 4; ++n) {
                        oAcc[n][0] *= sclo;
                        oAcc[n][1] *= sclo;
                        oAcc[n][2] *= schi;
                        oAcc[n][3] *= schi;
                    }
                    lAcc[0] *= sclo;
                    lAcc[1] *= sclo;
                    lAcc[2] *= schi;
                    lAcc[3] *= schi;
                }
            }

            // P per s-step: oAcc += P V ; lAcc += P * ones
            const float mlo2 = m_lo * L2E;
            const float mhi2 = m_hi * L2E;
            #pragma unroll
            for (int s = 0; s < 4; ++s) {
                unsigned aP[4];
                {
                    float e0 = fmaf(sAcc[2*s][0], L2E, -mlo2);
                    float e1 = fmaf(sAcc[2*s][1], L2E, -mlo2);
                    float e2 = fmaf(sAcc[2*s][2], L2E, -mhi2);
                    float e3 = fmaf(sAcc[2*s][3], L2E, -mhi2);
                    aP[0] = ex2h2(packh2(e0, e1));
                    aP[1] = ex2h2(packh2(e2, e3));
                    e0 = fmaf(sAcc[2*s+1][0], L2E, -mlo2);
                    e1 = fmaf(sAcc[2*s+1][1], L2E, -mlo2);
                    e2 = fmaf(sAcc[2*s+1][2], L2E, -mhi2);
                    e3 = fmaf(sAcc[2*s+1][3], L2E, -mhi2);
                    aP[2] = ex2h2(packh2(e0, e1));
                    aP[3] = ex2h2(packh2(e2, e3));
                }
                #pragma unroll
                for (int pr = 0; pr < 2; ++pr) {
                    unsigned bvf[4];
                    unsigned rv = vLdm + pr * (16 * VSTR * 2) + s * 32;
                    ldmx4(bvf[0], bvf[1], bvf[2], bvf[3], rv);
                    mma16816(oAcc[2*pr],   aP, &bvf[0], oAcc[2*pr]);
                    mma16816(oAcc[2*pr+1], aP, &bvf[2], oAcc[2*pr+1]);
                }
                mma16816(lAcc, aP, onesB, lAcc);
            }
        }

        if (kc < 7) {
            if (kc == 6) {
                CP_WAIT0();      // retire chunk 7 (no new issue at kc=6)
            } else {
                CP_WAIT1();      // retire chunk kc+1; kc+2 may stay in flight
            }
            __syncthreads();
        }
    }

    // l from the ones-MMA accumulator (k-reduction already complete)
    float l_lo = lAcc[0];
    float l_hi = lAcc[2];

    // Prefetch residual x for this tile (overlaps with the epilogue MMAs)
    float4 xv[8];
    {
        const float* xb = xg + (size_t)b * CI * HW + q0;
        #pragma unroll
        for (int i = 0; i < 8; ++i) {
            int idx = t + i * 256;
            int co = idx >> 5;
            int p4 = idx & 31;
            xv[i] = *(const float4*)&xb[(size_t)co * HW + p4 * 4];
        }
    }

    // normalize, stage Y as half into Ysm (= Qsm alias; per-warp rows)
    {
        float ilo = 1.0f / l_lo;
        float ihi = 1.0f / l_hi;
        int rlo = warp * 16 + (lane >> 2);
        int cb  = (lane & 3) * 2;
        #pragma unroll
        for (int n = 0; n < 4; ++n) {
            int c = n * 8 + cb;
            *(__half2*)&Ysm[rlo * QSTR + c] =
                __floats2half2_rn(oAcc[n][0] * ilo, oAcc[n][1] * ilo);
            *(__half2*)&Ysm[(rlo + 8) * QSTR + c] =
                __floats2half2_rn(oAcc[n][2] * ihi, oAcc[n][3] * ihi);
        }
    }
    __syncthreads();   // Ysm complete; Ksm/Vsm dead -> osm may overwrite

    // ---- fused output conv: out = Y * w_W^T + b_W + x ----
    unsigned aY0[4];
    unsigned aY1[4];
    {
        int arow = lane & 15;
        int acol = (lane >> 4) << 3;
        unsigned base = smem_u32(Ysm);
        unsigned ad = base + (((warp * 16 + arow) * QSTR + acol) << 1);
        ldmx4(aY0[0], aY0[1], aY0[2], aY0[3], ad);
        ldmx4(aY1[0], aY1[1], aY1[2], aY1[3], ad + 32);
    }

    const unsigned wBase = smem_u32(wsm) + ((brow * QSTR + bcol) << 1);
    float cf[8][4];
    #pragma unroll
    for (int nt = 0; nt < 8; ++nt) {
        cf[nt][0] = 0.f; cf[nt][1] = 0.f; cf[nt][2] = 0.f; cf[nt][3] = 0.f;
    }
    #pragma unroll
    for (int g = 0; g < 4; ++g) {
        unsigned bw[4];
        unsigned ra = wBase + g * (16 * QSTR * 2);
        ldmx4(bw[0], bw[1], bw[2], bw[3], ra);
        mma16816(cf[2*g],   aY0, &bw[0], cf[2*g]);
        mma16816(cf[2*g+1], aY0, &bw[2], cf[2*g+1]);
        ldmx4(bw[0], bw[1], bw[2], bw[3], ra + 32);
        mma16816(cf[2*g],   aY1, &bw[0], cf[2*g]);
        mma16816(cf[2*g+1], aY1, &bw[2], cf[2*g+1]);
    }

    // stage to osm[out][px] with bias
    {
        int rlo = warp * 16 + (lane >> 2);
        int cb  = (lane & 3) * 2;
        #pragma unroll
        for (int nt = 0; nt < 8; ++nt) {
            int c = nt * 8 + cb;
            float bc0 = bsd[c];
            float bc1 = bsd[c + 1];
            osm[c * OSTR + rlo]           = cf[nt][0] + bc0;
            osm[(c + 1) * OSTR + rlo]     = cf[nt][1] + bc1;
            osm[c * OSTR + rlo + 8]       = cf[nt][2] + bc0;
            osm[(c + 1) * OSTR + rlo + 8] = cf[nt][3] + bc1;
        }
    }
    __syncthreads();

    // residual add + store: 128 px x 64 out = 2048 float4
    {
        float* ob = outg + (size_t)b * CI * HW + q0;
        #pragma unroll
        for (int i = 0; i < 8; ++i) {
            int idx = t + i * 256;
            int co = idx >> 5;
            int p4 = idx & 31;
            float4 yv = *(const float4*)&osm[co * OSTR + p4 * 4];
            float4 ov;
            ov.x = yv.x + xv[i].x;
            ov.y = yv.y + xv[i].y;
            ov.z = yv.z + xv[i].z;
            ov.w = yv.w + xv[i].w;
            *(float4*)&ob[(size_t)co * HW + p4 * 4] = ov;
        }
    }
}

// ---------------------------------------------------------------------------
extern "C" void kernel_launch(void* const* d_in, const int* in_sizes, int n_in,
                              void* d_out, int out_size)
{
    const float* xg   = (const float*)d_in[0];
    const float* w_or = (const float*)d_in[1];
    const float* b_or = (const float*)d_in[2];
    const float* w_th = (const float*)d_in[3];
    const float* b_th = (const float*)d_in[4];
    const float* w_ph = (const float*)d_in[5];
    const float* b_ph = (const float*)d_in[6];
    const float* w_W  = (const float*)d_in[7];
    const float* b_W  = (const float*)d_in[8];
    float* outg = (float*)d_out;

    cudaFuncSetAttribute(qkv_kernel, cudaFuncAttributeMaxDynamicSharedMemorySize,
                         SMEM1_BYTES);
    cudaFuncSetAttribute(attn_kernel, cudaFuncAttributeMaxDynamicSharedMemorySize,
                         SMEM2_BYTES);

    qkv_kernel<<<dim3(32, NB), 256, SMEM1_BYTES>>>(xg, w_or, b_or, w_th, b_th,
                                                   w_ph, b_ph);
    attn_kernel<<<dim3(32, NB), 256, SMEM2_BYTES>>>(xg, w_W, b_W, outg);
}

// round 16
// speedup vs baseline: 1.0287x; 1.0287x over previous
#include <cuda_runtime.h>
#include <cuda_fp16.h>

#define NB   16
#define CI   64
#define CM   32
#define HW   4096
#define NKV  1024

// Scratch (static device globals; no allocation allowed)
__device__ __half Qh[(size_t)NB * HW * CM];    // [B][4096 q][32 c]
__device__ __half Kh[(size_t)NB * NKV * CM];   // [B][1024 kv][32 c]
__device__ __half Vth[(size_t)NB * CM * NKV];  // [B][32 c][1024 kv]

// ---------------------------------------------------------------------------
// helpers
// ---------------------------------------------------------------------------
__device__ __forceinline__ unsigned smem_u32(const void* p) {
    return (unsigned)__cvta_generic_to_shared(p);
}

__device__ __forceinline__ void ldmx4(unsigned& r0, unsigned& r1, unsigned& r2,
                                      unsigned& r3, unsigned addr) {
    asm volatile("ldmatrix.sync.aligned.m8n8.x4.shared.b16 {%0,%1,%2,%3}, [%4];\n"
                 : "=r"(r0), "=r"(r1), "=r"(r2), "=r"(r3) : "r"(addr));
}

__device__ __forceinline__ void mma16816(float* dd, const unsigned* aa,
                                         const unsigned* bb, const float* cc) {
    asm volatile(
        "mma.sync.aligned.m16n8k16.row.col.f32.f16.f16.f32 "
        "{%0,%1,%2,%3},{%4,%5,%6,%7},{%8,%9},{%10,%11,%12,%13};\n"
        : "=f"(dd[0]), "=f"(dd[1]), "=f"(dd[2]), "=f"(dd[3])
        : "r"(aa[0]), "r"(aa[1]), "r"(aa[2]), "r"(aa[3]),
          "r"(bb[0]), "r"(bb[1]),
          "f"(cc[0]), "f"(cc[1]), "f"(cc[2]), "f"(cc[3]));
}

__device__ __forceinline__ unsigned packh2(float av, float bv) {
    __half2 hh = __floats2half2_rn(av, bv);
    return *(unsigned*)&hh;
}

__device__ __forceinline__ unsigned ex2h2(unsigned in) {
    unsigned r;
    asm("ex2.approx.f16x2 %0, %1;\n" : "=r"(r) : "r"(in));
    return r;
}

#define CP_ASYNC16(sa, g) \
    asm volatile("cp.async.cg.shared.global [%0], [%1], 16;\n" :: "r"(sa), "l"(g))
#define CP_COMMIT() asm volatile("cp.async.commit_group;\n")
#define CP_WAIT0()  asm volatile("cp.async.wait_group 0;\n" ::: "memory")
#define CP_WAIT1()  asm volatile("cp.async.wait_group 1;\n" ::: "memory")

#define L2E 1.4426950408889634f
#define ONES_H2 0x3C003C00u   // fp16 {1.0, 1.0}

// ---------------------------------------------------------------------------
// Kernel 1: qkv via tensor cores. 256 threads = 8 warps (16-px strip each).
// grid (32 row-pairs, B). 4 blocks/SM.
// ---------------------------------------------------------------------------
#define XSTR 72
#define WSTR 72
#define QKV_XSH   0
#define QKV_WSH   18432
#define QKV_BIAS  32256
#define SMEM1_BYTES (32256 + 384)

__global__ void __launch_bounds__(256, 4) qkv_kernel(
    const float* __restrict__ xg,
    const float* __restrict__ w_or, const float* __restrict__ b_or,
    const float* __restrict__ w_th, const float* __restrict__ b_th,
    const float* __restrict__ w_ph, const float* __restrict__ b_ph)
{
    extern __shared__ char smraw[];
    __half* xsh  = (__half*)(smraw + QKV_XSH);    // [128 px][XSTR]
    __half* wsh  = (__half*)(smraw + QKV_WSH);    // [96 out][WSTR]
    float*  bias = (float*)(smraw + QKV_BIAS);    // [96]
    float*  stg  = (float*)(smraw + QKV_XSH);     // alias: [128 px][33] fp32

    const int t    = threadIdx.x;
    const int warp = t >> 5;
    const int lane = t & 31;
    const int hp   = blockIdx.x;
    const int b    = blockIdx.y;

    for (int i = t; i < 2048; i += 256) {
        int r = i >> 6;
        int c = i & 63;
        wsh[r * WSTR + c]        = __float2half(w_th[i]);
        wsh[(32 + r) * WSTR + c] = __float2half(w_ph[i]);
        wsh[(64 + r) * WSTR + c] = __float2half(w_or[i]);
    }
    if (t < 32) {
        bias[t]      = b_th[t];
        bias[32 + t] = b_ph[t];
        bias[64 + t] = b_or[t];
    }

    {
        const int p0 = (t & 31) * 4;
        const int c0 = (t >> 5) * 8;
        const float* xb = xg + ((size_t)b * CI + c0) * HW + hp * 128 + p0;
        unsigned wbuf[4][4];
        #pragma unroll
        for (int cc = 0; cc < 4; ++cc) {
            float4 va = *(const float4*)xb;
            float4 vb = *(const float4*)(xb + HW);
            xb += 2 * HW;
            wbuf[0][cc] = packh2(va.x, vb.x);
            wbuf[1][cc] = packh2(va.y, vb.y);
            wbuf[2][cc] = packh2(va.z, vb.z);
            wbuf[3][cc] = packh2(va.w, vb.w);
        }
        #pragma unroll
        for (int j = 0; j < 4; ++j) {
            uint4 u0;
            u0.x = wbuf[j][0]; u0.y = wbuf[j][1]; u0.z = wbuf[j][2]; u0.w = wbuf[j][3];
            *(uint4*)&xsh[(p0 + j) * XSTR + c0] = u0;
        }
    }
    __syncthreads();

    unsigned aX[4][4];
    {
        int arow = lane & 15;
        int acol = (lane >> 4) << 3;
        unsigned base = smem_u32(xsh);
        #pragma unroll
        for (int k = 0; k < 4; ++k) {
            unsigned ad = base +
                (((warp * 16 + arow) * XSTR + k * 16 + acol) << 1);
            ldmx4(aX[k][0], aX[k][1], aX[k][2], aX[k][3], ad);
        }
    }
    __syncthreads();   // xsh is now dead; stg may overwrite it

    const int brow = ((lane >> 4) << 3) + (lane & 7);
    const int bcol = ((lane >> 3) & 1) << 3;
    const unsigned wshBase = smem_u32(wsh);

    #pragma unroll 1
    for (int g = 0; g < 3; ++g) {
        float cf[4][4];
        #pragma unroll
        for (int nt = 0; nt < 4; ++nt) {
            cf[nt][0] = 0.f; cf[nt][1] = 0.f; cf[nt][2] = 0.f; cf[nt][3] = 0.f;
        }
        #pragma unroll
        for (int nt2 = 0; nt2 < 2; ++nt2) {
            #pragma unroll
            for (int k = 0; k < 4; ++k) {
                unsigned bw[4];
                unsigned ra = wshBase +
                    (((g * 32 + nt2 * 16 + brow) * WSTR + k * 16 + bcol) << 1);
                ldmx4(bw[0], bw[1], bw[2], bw[3], ra);
                mma16816(cf[nt2*2],   aX[k], &bw[0], cf[nt2*2]);
                mma16816(cf[nt2*2+1], aX[k], &bw[2], cf[nt2*2+1]);
            }
        }
        #pragma unroll
        for (int nt = 0; nt < 4; ++nt) {
            int o0 = g * 32 + nt * 8 + (lane & 3) * 2;
            cf[nt][0] += bias[o0];
            cf[nt][1] += bias[o0 + 1];
            cf[nt][2] += bias[o0];
            cf[nt][3] += bias[o0 + 1];
        }

        if (g == 0) {
            __half2* Qb = (__half2*)(Qh + ((size_t)b * HW + hp * 128) * CM);
            int row = warp * 16 + (lane >> 2);
            #pragma unroll
            for (int nt = 0; nt < 4; ++nt) {
                int cp = (nt * 8 + (lane & 3) * 2) >> 1;
                Qb[row * 16 + cp]       = __floats2half2_rn(cf[nt][0], cf[nt][1]);
                Qb[(row + 8) * 16 + cp] = __floats2half2_rn(cf[nt][2], cf[nt][3]);
            }
        } else {
            int row = warp * 16 + (lane >> 2);
            #pragma unroll
            for (int nt = 0; nt < 4; ++nt) {
                int c0 = nt * 8 + (lane & 3) * 2;
                stg[row * 33 + c0]           = cf[nt][0];
                stg[row * 33 + c0 + 1]       = cf[nt][1];
                stg[(row + 8) * 33 + c0]     = cf[nt][2];
                stg[(row + 8) * 33 + c0 + 1] = cf[nt][3];
            }
            __syncthreads();
            if (g == 1) {
                #pragma unroll
                for (int i = 0; i < 4; ++i) {
                    int idx = t + i * 256;
                    int kw = idx >> 5;
                    int o  = idx & 31;
                    float mv = fmaxf(
                        fmaxf(stg[(2*kw) * 33 + o], stg[(2*kw + 1) * 33 + o]),
                        fmaxf(stg[(64 + 2*kw) * 33 + o], stg[(65 + 2*kw) * 33 + o]));
                    Kh[((size_t)b * NKV + hp * 32 + kw) * CM + o] = __float2half(mv);
                }
            } else {
                #pragma unroll
                for (int i = 0; i < 4; ++i) {
                    int idx = t + i * 256;
                    int o  = idx >> 5;
                    int kw = idx & 31;
                    float mv = fmaxf(
                        fmaxf(stg[(2*kw) * 33 + o], stg[(2*kw + 1) * 33 + o]),
                        fmaxf(stg[(64 + 2*kw) * 33 + o], stg[(65 + 2*kw) * 33 + o]));
                    Vth[((size_t)b * CM + o) * NKV + hp * 32 + kw] = __float2half(mv);
                }
            }
            __syncthreads();
        }
    }
}

// ---------------------------------------------------------------------------
// Kernel 2: FUSED attention + output conv + residual. 256-q tiles.
// grid (16, B) = 256 blocks, 2 blocks/SM -> SINGLE WAVE (296 slots).
// Each warp: 32 q rows as two sequential m-tiles (independent streams ->
// cross-m-tile ILP). 128-kv buffers, 3-stage depth-2 cp.async pipeline.
// ---------------------------------------------------------------------------
#define QSTR 40
#define VSTR 136                   // 128 kv + 8 pad halfs
#define OSTR 260                   // 256 px + 4 pad floats
#define AT_QSM  0                              // [256 q][QSTR] = 20480
#define AT_WSM  20480                          // [64][QSTR] = 5120
#define AT_BSD  25600                          // 256
#define AT_KSM  25856
#define KBUF_B  (128 * QSTR * 2)   // 10240
#define VBUF_B  (32 * VSTR * 2)    // 8704
#define AT_VSM  (AT_KSM + 3 * KBUF_B)          // 56576
#define AT_OSM  25856              // alias over Ksm/Vsm (dead after mainloop)
#define SMEM2_BYTES (AT_OSM + 64 * OSTR * 4)   // 92416

__global__ void __launch_bounds__(256, 2) attn_kernel(
    const float* __restrict__ xg, const float* __restrict__ w_W,
    const float* __restrict__ b_W, float* __restrict__ outg)
{
    extern __shared__ char atraw[];
    __half* Qsm = (__half*)(atraw + AT_QSM);   // [256 q][QSTR]; Ysm in epilogue
    __half* wsm = (__half*)(atraw + AT_WSM);   // [64 out][QSTR]
    float*  bsd = (float*)(atraw + AT_BSD);    // [64]
    __half* Ksm = (__half*)(atraw + AT_KSM);   // 3 x [128 kv][QSTR]
    __half* Vsm = (__half*)(atraw + AT_VSM);   // 3 x [32 c][VSTR]
    float*  osm = (float*)(atraw + AT_OSM);    // [64 out][OSTR] (alias)
    __half* Ysm = Qsm;

    const int t    = threadIdx.x;
    const int warp = t >> 5;
    const int lane = t & 31;
    const int b    = blockIdx.y;
    const int q0   = blockIdx.x * 256;

    const __half* kSrcB = Kh + (size_t)b * NKV * CM;
    const __half* vSrcB = Vth + (size_t)b * CM * NKV;

    // prologue: Q (1024 uint4) + chunk0 (group 0), chunk1 (group 1)
    {
        #pragma unroll
        for (int i = 0; i < 4; ++i) {
            int idx = t + i * 256;
            int row = idx >> 2;
            int seg = idx & 3;
            CP_ASYNC16(smem_u32(&Qsm[row * QSTR + seg * 8]),
                       Qh + ((size_t)b * HW + q0 + row) * CM + seg * 8);
        }
        #pragma unroll
        for (int i = 0; i < 2; ++i) {
            int idx = t + i * 256;
            int kr = idx >> 2, ks = idx & 3;
            CP_ASYNC16(smem_u32(&Ksm[kr * QSTR + ks * 8]),
                       kSrcB + (size_t)kr * CM + ks * 8);
            int vr = idx >> 4, vs = idx & 15;
            CP_ASYNC16(smem_u32(&Vsm[vr * VSTR + vs * 8]),
                       vSrcB + (size_t)vr * NKV + vs * 8);
        }
        CP_COMMIT();                               // group: Q + chunk 0
        #pragma unroll
        for (int i = 0; i < 2; ++i) {
            int idx = t + i * 256;
            int kr = idx >> 2, ks = idx & 3;
            CP_ASYNC16(smem_u32(&Ksm[kr * QSTR + ks * 8]) + KBUF_B,
                       kSrcB + (size_t)(kr + 128) * CM + ks * 8);
            int vr = idx >> 4, vs = idx & 15;
            CP_ASYNC16(smem_u32(&Vsm[vr * VSTR + vs * 8]) + VBUF_B,
                       vSrcB + (size_t)vr * NKV + 128 + vs * 8);
        }
        CP_COMMIT();                               // group: chunk 1
        for (int i = t; i < 2048; i += 256) {
            wsm[(i >> 5) * QSTR + (i & 31)] = __float2half(w_W[i]);
        }
        if (t < 64) {
            bsd[t] = b_W[t];
        }
        CP_WAIT1();                                // Q + chunk 0 complete
        __syncthreads();
    }

    // A-operand (Q) fragments: 2 m-tiles x 2 k-steps
    unsigned aQ[2][2][4];
    {
        int arow = lane & 15;
        int acol = (lane >> 4) << 3;
        unsigned base = smem_u32(Qsm);
        #pragma unroll
        for (int mt = 0; mt < 2; ++mt) {
            unsigned ad0 = base + (((warp * 32 + mt * 16 + arow) * QSTR + acol) << 1);
            ldmx4(aQ[mt][0][0], aQ[mt][0][1], aQ[mt][0][2], aQ[mt][0][3], ad0);
            ldmx4(aQ[mt][1][0], aQ[mt][1][1], aQ[mt][1][2], aQ[mt][1][3], ad0 + 32);
        }
    }

    const int brow = ((lane >> 4) << 3) + (lane & 7);
    const int bcol = ((lane >> 3) & 1) << 3;
    const unsigned kLdm0 = smem_u32(Ksm) + ((brow * QSTR + bcol) << 1);
    const unsigned vLdm0 = smem_u32(Vsm) + ((brow * VSTR + bcol) << 1);

    // per-thread cp.async coords for the mainloop prefetch
    const int kRow = t >> 2;
    const int kSeg = t & 3;
    const int vRow = t >> 4;
    const int vSeg = t & 15;
    const unsigned kDstA = smem_u32(&Ksm[kRow * QSTR + kSeg * 8]);
    const unsigned kDstB = smem_u32(&Ksm[(kRow + 64) * QSTR + kSeg * 8]);
    const unsigned vDstA = smem_u32(&Vsm[vRow * VSTR + vSeg * 8]);
    const unsigned vDstB = smem_u32(&Vsm[(vRow + 16) * VSTR + vSeg * 8]);

    float oAcc[2][4][4];
    float lAcc[2][4];
    float mRun[2][2];      // [mt][0]=m_lo, [mt][1]=m_hi
    #pragma unroll
    for (int mt = 0; mt < 2; ++mt) {
        #pragma unroll
        for (int n = 0; n < 4; ++n) {
            oAcc[mt][n][0] = 0.f; oAcc[mt][n][1] = 0.f;
            oAcc[mt][n][2] = 0.f; oAcc[mt][n][3] = 0.f;
        }
        lAcc[mt][0] = 0.f; lAcc[mt][1] = 0.f; lAcc[mt][2] = 0.f; lAcc[mt][3] = 0.f;
        mRun[mt][0] = -1e30f;
        mRun[mt][1] = -1e30f;
    }
    const unsigned onesB[2] = { ONES_H2, ONES_H2 };

    unsigned kOffCur = 0, vOffCur = 0;
    unsigned kOffPre = 2 * KBUF_B, vOffPre = 2 * VBUF_B;

    for (int kc = 0; kc < 8; ++kc) {
        if (kc < 6) {
            const __half* kP = kSrcB + (size_t)(kc + 2) * 128 * CM;
            const __half* vP = vSrcB + (size_t)(kc + 2) * 128;
            CP_ASYNC16(kDstA + kOffPre, kP + (size_t)kRow * CM + kSeg * 8);
            CP_ASYNC16(kDstB + kOffPre, kP + (size_t)(kRow + 64) * CM + kSeg * 8);
            CP_ASYNC16(vDstA + vOffPre, vP + (size_t)vRow * NKV + vSeg * 8);
            CP_ASYNC16(vDstB + vOffPre, vP + (size_t)(vRow + 16) * NKV + vSeg * 8);
            CP_COMMIT();
            kOffPre = (kOffPre == 2 * KBUF_B) ? 0u : kOffPre + KBUF_B;
            vOffPre = (vOffPre == 2 * VBUF_B) ? 0u : vOffPre + VBUF_B;
        }
        const unsigned kLdmBuf = kLdm0 + kOffCur;
        const unsigned vLdmBuf = vLdm0 + vOffCur;
        kOffCur = (kOffCur == 2 * KBUF_B) ? 0u : kOffCur + KBUF_B;
        vOffCur = (vOffCur == 2 * VBUF_B) ? 0u : vOffCur + VBUF_B;

        // two 64-kv sub-iterations per buffer; two m-tiles per sub-iteration
        #pragma unroll 1
        for (int h = 0; h < 2; ++h) {
            const unsigned kLdm = kLdmBuf + h * (64 * QSTR * 2);
            const unsigned vLdm = vLdmBuf + h * 128;

            #pragma unroll
            for (int mt = 0; mt < 2; ++mt) {
                float sAcc[8][4];
                #pragma unroll
                for (int j = 0; j < 8; ++j) {
                    sAcc[j][0] = 0.f; sAcc[j][1] = 0.f;
                    sAcc[j][2] = 0.f; sAcc[j][3] = 0.f;
                }
                #pragma unroll
                for (int g = 0; g < 4; ++g) {
                    unsigned bkf[4];
                    unsigned ra = kLdm + g * (16 * QSTR * 2);
                    ldmx4(bkf[0], bkf[1], bkf[2], bkf[3], ra);
                    mma16816(sAcc[2*g],   aQ[mt][0], &bkf[0], sAcc[2*g]);
                    mma16816(sAcc[2*g+1], aQ[mt][0], &bkf[2], sAcc[2*g+1]);
                    ldmx4(bkf[0], bkf[1], bkf[2], bkf[3], ra + 32);
                    mma16816(sAcc[2*g],   aQ[mt][1], &bkf[0], sAcc[2*g]);
                    mma16816(sAcc[2*g+1], aQ[mt][1], &bkf[2], sAcc[2*g+1]);
                }

                float mlo = -1e30f;
                float mhi = -1e30f;
                #pragma unroll
                for (int j = 0; j < 8; ++j) {
                    mlo = fmaxf(mlo, fmaxf(sAcc[j][0], sAcc[j][1]));
                    mhi = fmaxf(mhi, fmaxf(sAcc[j][2], sAcc[j][3]));
                }

                bool below = (mlo <= mRun[mt][0]) && (mhi <= mRun[mt][1]);
                if (!__all_sync(0xffffffffu, below)) {
                    unsigned mp = packh2(mlo, mhi);
                    __half2 mh = *(__half2*)&mp;
                    unsigned ms1 = __shfl_xor_sync(0xffffffffu, mp, 1);
                    mh = __hmax2(mh, *(__half2*)&ms1);
                    unsigned mhu = *(unsigned*)&mh;
                    unsigned ms2 = __shfl_xor_sync(0xffffffffu, mhu, 2);
                    mh = __hmax2(mh, *(__half2*)&ms2);
                    mlo = __low2float(mh);
                    mhi = __high2float(mh);

                    float nmlo = fmaxf(mRun[mt][0], mlo);
                    float nmhi = fmaxf(mRun[mt][1], mhi);
                    float sclo = __expf(mRun[mt][0] - nmlo);
                    float schi = __expf(mRun[mt][1] - nmhi);
                    mRun[mt][0] = nmlo;
                    mRun[mt][1] = nmhi;

                    bool noup = (sclo == 1.0f) && (schi == 1.0f);
                    if (!__all_sync(0xffffffffu, noup)) {
                        #pragma unroll
                        for (int n = 0; n < 4; ++n) {
                            oAcc[mt][n][0] *= sclo;
                            oAcc[mt][n][1] *= sclo;
                            oAcc[mt][n][2] *= schi;
                            oAcc[mt][n][3] *= schi;
                        }
                        lAcc[mt][0] *= sclo;
                        lAcc[mt][1] *= sclo;
                        lAcc[mt][2] *= schi;
                        lAcc[mt][3] *= schi;
                    }
                }

                const float mlo2 = mRun[mt][0] * L2E;
                const float mhi2 = mRun[mt][1] * L2E;
                #pragma unroll
                for (int s = 0; s < 4; ++s) {
                    unsigned aP[4];
                    {
                        float e0 = fmaf(sAcc[2*s][0], L2E, -mlo2);
                        float e1 = fmaf(sAcc[2*s][1], L2E, -mlo2);
                        float e2 = fmaf(sAcc[2*s][2], L2E, -mhi2);
                        float e3 = fmaf(sAcc[2*s][3], L2E, -mhi2);
                        aP[0] = ex2h2(packh2(e0, e1));
                        aP[1] = ex2h2(packh2(e2, e3));
                        e0 = fmaf(sAcc[2*s+1][0], L2E, -mlo2);
                        e1 = fmaf(sAcc[2*s+1][1], L2E, -mlo2);
                        e2 = fmaf(sAcc[2*s+1][2], L2E, -mhi2);
                        e3 = fmaf(sAcc[2*s+1][3], L2E, -mhi2);
                        aP[2] = ex2h2(packh2(e0, e1));
                        aP[3] = ex2h2(packh2(e2, e3));
                    }
                    #pragma unroll
                    for (int pr = 0; pr < 2; ++pr) {
                        unsigned bvf[4];
                        unsigned rv = vLdm + pr * (16 * VSTR * 2) + s * 32;
                        ldmx4(bvf[0], bvf[1], bvf[2], bvf[3], rv);
                        mma16816(oAcc[mt][2*pr],   aP, &bvf[0], oAcc[mt][2*pr]);
                        mma16816(oAcc[mt][2*pr+1], aP, &bvf[2], oAcc[mt][2*pr+1]);
                    }
                    mma16816(lAcc[mt], aP, onesB, lAcc[mt]);
                }
            }
        }

        if (kc < 7) {
            if (kc == 6) {
                CP_WAIT0();
            } else {
                CP_WAIT1();
            }
            __syncthreads();
        }
    }

    // normalize, stage Y as half into Ysm (= Qsm alias; per-warp rows)
    {
        #pragma unroll
        for (int mt = 0; mt < 2; ++mt) {
            float ilo = 1.0f / lAcc[mt][0];
            float ihi = 1.0f / lAcc[mt][2];
            int rlo = warp * 32 + mt * 16 + (lane >> 2);
            int cb  = (lane & 3) * 2;
            #pragma unroll
            for (int n = 0; n < 4; ++n) {
                int c = n * 8 + cb;
                *(__half2*)&Ysm[rlo * QSTR + c] =
                    __floats2half2_rn(oAcc[mt][n][0] * ilo, oAcc[mt][n][1] * ilo);
                *(__half2*)&Ysm[(rlo + 8) * QSTR + c] =
                    __floats2half2_rn(oAcc[mt][n][2] * ihi, oAcc[mt][n][3] * ihi);
            }
        }
    }
    __syncthreads();   // Ysm complete; Ksm/Vsm dead -> osm may overwrite

    // ---- fused output conv: out = Y * w_W^T + b_W + x ----
    {
        #pragma unroll 1
        for (int mt = 0; mt < 2; ++mt) {
            unsigned aY0[4];
            unsigned aY1[4];
            {
                int arow = lane & 15;
                int acol = (lane >> 4) << 3;
                unsigned ad = smem_u32(Ysm) +
                    (((warp * 32 + mt * 16 + arow) * QSTR + acol) << 1);
                ldmx4(aY0[0], aY0[1], aY0[2], aY0[3], ad);
                ldmx4(aY1[0], aY1[1], aY1[2], aY1[3], ad + 32);
            }
            const unsigned wBase = smem_u32(wsm) + ((brow * QSTR + bcol) << 1);
            float cf[8][4];
            #pragma unroll
            for (int nt = 0; nt < 8; ++nt) {
                cf[nt][0] = 0.f; cf[nt][1] = 0.f; cf[nt][2] = 0.f; cf[nt][3] = 0.f;
            }
            #pragma unroll
            for (int g = 0; g < 4; ++g) {
                unsigned bw[4];
                unsigned ra = wBase + g * (16 * QSTR * 2);
                ldmx4(bw[0], bw[1], bw[2], bw[3], ra);
                mma16816(cf[2*g],   aY0, &bw[0], cf[2*g]);
                mma16816(cf[2*g+1], aY0, &bw[2], cf[2*g+1]);
                ldmx4(bw[0], bw[1], bw[2], bw[3], ra + 32);
                mma16816(cf[2*g],   aY1, &bw[0], cf[2*g]);
                mma16816(cf[2*g+1], aY1, &bw[2], cf[2*g+1]);
            }
            {
                int rlo = warp * 32 + mt * 16 + (lane >> 2);
                int cb  = (lane & 3) * 2;
                #pragma unroll
                for (int nt = 0; nt < 8; ++nt) {
                    int c = nt * 8 + cb;
                    float bc0 = bsd[c];
                    float bc1 = bsd[c + 1];
                    osm[c * OSTR + rlo]           = cf[nt][0] + bc0;
                    osm[(c + 1) * OSTR + rlo]     = cf[nt][1] + bc1;
                    osm[c * OSTR + rlo + 8]       = cf[nt][2] + bc0;
                    osm[(c + 1) * OSTR + rlo + 8] = cf[nt][3] + bc1;
                }
            }
        }
    }
    __syncthreads();

    // residual add + store: 256 px x 64 out = 4096 float4
    {
        const float* xb = xg + (size_t)b * CI * HW + q0;
        float* ob = outg + (size_t)b * CI * HW + q0;
        #pragma unroll
        for (int i = 0; i < 16; ++i) {
            int idx = t + i * 256;
            int co = idx >> 6;
            int p4 = idx & 63;
            float4 yv = *(const float4*)&osm[co * OSTR + p4 * 4];
            size_t gi = (size_t)co * HW + p4 * 4;
            float4 xvv = *(const float4*)&xb[gi];
            float4 ov;
            ov.x = yv.x + xvv.x;
            ov.y = yv.y + xvv.y;
            ov.z = yv.z + xvv.z;
            ov.w = yv.w + xvv.w;
            *(float4*)&ob[gi] = ov;
        }
    }
}

// ---------------------------------------------------------------------------
extern "C" void kernel_launch(void* const* d_in, const int* in_sizes, int n_in,
                              void* d_out, int out_size)
{
    const float* xg   = (const float*)d_in[0];
    const float* w_or = (const float*)d_in[1];
    const float* b_or = (const float*)d_in[2];
    const float* w_th = (const float*)d_in[3];
    const float* b_th = (const float*)d_in[4];
    const float* w_ph = (const float*)d_in[5];
    const float* b_ph = (const float*)d_in[6];
    const float* w_W  = (const float*)d_in[7];
    const float* b_W  = (const float*)d_in[8];
    float* outg = (float*)d_out;

    cudaFuncSetAttribute(qkv_kernel, cudaFuncAttributeMaxDynamicSharedMemorySize,
                         SMEM1_BYTES);
    cudaFuncSetAttribute(attn_kernel, cudaFuncAttributeMaxDynamicSharedMemorySize,
                         SMEM2_BYTES);

    qkv_kernel<<<dim3(32, NB), 256, SMEM1_BYTES>>>(xg, w_or, b_or, w_th, b_th,
                                                   w_ph, b_ph);
    attn_kernel<<<dim3(16, NB), 256, SMEM2_BYTES>>>(xg, w_W, b_W, outg);
}